// round 2
// baseline (speedup 1.0000x reference)
#include <cuda_runtime.h>
#include <cuda_bf16.h>
#include <math.h>

// Problem constants
#define Bb   64
#define NPG  400
#define Kk   250
#define Ff   64
#define LIN  16000
#define Hh   8000
#define Nn   (Bb*NPG)        // 25600
#define BN_EPS 1e-5f

// Scratch (device globals; no allocation allowed)
__device__ float g_xn[Bb*LIN];      // fp32 now (tf32 MMA path)
__device__ float g_h[Bb*Hh];
__device__ float g_logits[Bb];

// ---------------------------------------------------------------------------
// Kernel 1: fused scores + per-graph top-K (bitonic) + gather + tanh rescale
//           + BatchNorm -> fp32 xn
// ---------------------------------------------------------------------------
__global__ void k_pool(const float* __restrict__ feat, const float* __restrict__ w,
                       const float* __restrict__ bn_mean, const float* __restrict__ bn_var,
                       const float* __restrict__ bn_gamma, const float* __restrict__ bn_beta) {
    __shared__ float sv[512];
    __shared__ int   si[512];
    __shared__ float s_inv;
    int tid = threadIdx.x, b = blockIdx.x;
    int warp = tid >> 5, lane = tid & 31;

    if (tid == 0) {
        float s = 0.f;
        #pragma unroll
        for (int i = 0; i < Ff; i++) s += w[i] * w[i];
        s_inv = rsqrtf(s);
    }

    // scores: warp-parallel dot products, 16 warps x 25 nodes
    const float* xg = feat + (size_t)11 * Nn * Ff + (size_t)b * NPG * Ff;
    float wl0 = w[lane], wl1 = w[lane + 32];
    for (int nd = warp; nd < NPG; nd += 16) {
        const float* x = xg + (size_t)nd * Ff;
        float v = x[lane] * wl0 + x[lane + 32] * wl1;
        #pragma unroll
        for (int o = 16; o > 0; o >>= 1) v += __shfl_down_sync(0xffffffffu, v, o);
        if (lane == 0) sv[nd] = v;
    }
    if (tid >= NPG) sv[tid] = __int_as_float(0xff800000);  // -inf pad
    si[tid] = tid;
    __syncthreads();

    // Bitonic sort: value descending, index ascending on ties
    for (int k = 2; k <= 512; k <<= 1) {
        for (int j = k >> 1; j > 0; j >>= 1) {
            int ixj = tid ^ j;
            if (ixj > tid) {
                float va = sv[tid], vb = sv[ixj];
                int   ia = si[tid], ib = si[ixj];
                bool aFirst = (va > vb) || (va == vb && ia < ib);
                bool bFirst = (vb > va) || (vb == va && ib < ia);
                bool desc = ((tid & k) == 0);
                bool sw = desc ? bFirst : aFirst;
                if (sw) { sv[tid] = vb; sv[ixj] = va; si[tid] = ib; si[ixj] = ia; }
            }
            __syncthreads();
        }
    }

    float inv = s_inv;
    for (int i = tid; i < LIN; i += 512) {
        int r = i >> 6, f = i & 63;
        float sval = tanhf(sv[r] * inv);
        float xv = xg[si[r] * Ff + f];
        float xn = (xv * sval - bn_mean[i]) * rsqrtf(bn_var[i] + BN_EPS) * bn_gamma[i] + bn_beta[i];
        g_xn[(size_t)b * LIN + i] = xn;
    }
}

// ---------------------------------------------------------------------------
// Kernel 2: zero the split-K accumulator
// ---------------------------------------------------------------------------
__global__ void k_zero() {
    int i = blockIdx.x * blockDim.x + threadIdx.x;
    if (i < Bb * Hh) g_h[i] = 0.f;
}

// ---------------------------------------------------------------------------
// Kernel 3: GEMM1.  h[m,j] += sum_k xn[m,k] * W1[j,k]
// fp32 streamed via cp.async into a 3-stage smem ring, tf32 m16n8k8 MMA.
// Block: 256 threads (8 warps), BN=128 j, all 64 m, BK=32, split-K=4.
// Warp (wm, wj) = (warp>>2, warp&3): 32 m-rows x 32 j-cols (2 mt x 4 nt tiles).
// ---------------------------------------------------------------------------
#define BN1    128
#define BK1    32
#define KSPLIT 4
#define KCHUNK (LIN / KSPLIT)   // 4000
#define ITERS  (KCHUNK / BK1)   // 125
#define NSTAGE 3
#define PADK   36               // floats per smem row (bank-conflict-free, 144B = 9x16B)
#define STG_W  (BN1 * PADK)     // 4608 floats
#define STG_X  (64 * PADK)      // 2304 floats
#define STG_SZ (STG_W + STG_X)  // 6912 floats
#define SMEM1_BYTES (NSTAGE * STG_SZ * 4)  // 82944

__device__ __forceinline__ void mma_tf32(float* d, unsigned a0, unsigned a1,
                                         unsigned a2, unsigned a3,
                                         unsigned b0, unsigned b1) {
    asm volatile(
        "mma.sync.aligned.m16n8k8.row.col.f32.tf32.tf32.f32 "
        "{%0,%1,%2,%3}, {%4,%5,%6,%7}, {%8,%9}, {%0,%1,%2,%3};\n"
        : "+f"(d[0]), "+f"(d[1]), "+f"(d[2]), "+f"(d[3])
        : "r"(a0), "r"(a1), "r"(a2), "r"(a3), "r"(b0), "r"(b1));
}

__device__ __forceinline__ void cp16(unsigned smem_addr, const void* gptr) {
    asm volatile("cp.async.cg.shared.global [%0], [%1], 16;\n"
                 :: "r"(smem_addr), "l"(gptr));
}

__global__ __launch_bounds__(256, 2) void k_gemm1(const float* __restrict__ W1) {
    extern __shared__ float sm[];
    unsigned smbase = (unsigned)__cvta_generic_to_shared(sm);

    int tid  = threadIdx.x;
    int warp = tid >> 5, lane = tid & 31;
    int wm = warp >> 2, wj = warp & 3;
    int gi = lane >> 2, qi = lane & 3;
    int jbase = blockIdx.x * BN1;
    int kbase = blockIdx.y * KCHUNK;

    // cp.async source mapping
    // W: chunks c = tid + i*256 (i<4): row = c>>3 (0..127), kc = (c&7)*4
    // X: chunks c = tid, tid+256:      row = c>>3 (0..63),  kc = (c&7)*4
    const float* wsrc[4];
    unsigned     wdst[4];
    #pragma unroll
    for (int i = 0; i < 4; i++) {
        int c = tid + i * 256;
        int row = c >> 3, kc = (c & 7) * 4;
        int j = jbase + row; if (j > Hh - 1) j = Hh - 1;
        wsrc[i] = W1 + (size_t)j * LIN + kbase + kc;
        wdst[i] = smbase + (row * PADK + kc) * 4;
    }
    const float* xsrc[2];
    unsigned     xdst[2];
    #pragma unroll
    for (int i = 0; i < 2; i++) {
        int c = tid + i * 256;
        int row = c >> 3, kc = (c & 7) * 4;
        xsrc[i] = g_xn + (size_t)row * LIN + kbase + kc;
        xdst[i] = smbase + (STG_W + row * PADK + kc) * 4;
    }

    float acc[2][4][4];
    #pragma unroll
    for (int a = 0; a < 2; a++)
        #pragma unroll
        for (int b = 0; b < 4; b++)
            #pragma unroll
            for (int q = 0; q < 4; q++) acc[a][b][q] = 0.f;

    // prologue: issue stages 0, 1
    #pragma unroll
    for (int s = 0; s < NSTAGE - 1; s++) {
        int koff = s * BK1;
        unsigned sb = (unsigned)(s * STG_SZ * 4);
        #pragma unroll
        for (int i = 0; i < 4; i++) cp16(wdst[i] + sb, wsrc[i] + koff);
        #pragma unroll
        for (int i = 0; i < 2; i++) cp16(xdst[i] + sb, xsrc[i] + koff);
        asm volatile("cp.async.commit_group;\n");
    }

    const float* sWb = sm;
    const float* sXb = sm + STG_W;

    for (int it = 0; it < ITERS; it++) {
        asm volatile("cp.async.wait_group 1;\n");
        __syncthreads();

        int st = it % NSTAGE;
        const float* sW = sWb + st * STG_SZ;
        const float* sX = sXb + st * STG_SZ;

        #pragma unroll
        for (int ks = 0; ks < 4; ks++) {
            int k0 = ks * 8;
            unsigned a0[2], a1[2], a2[2], a3[2];
            #pragma unroll
            for (int mt = 0; mt < 2; mt++) {
                const float* ap = sX + (wm * 32 + mt * 16 + gi) * PADK + k0 + qi;
                a0[mt] = __float_as_uint(ap[0]);
                a1[mt] = __float_as_uint(ap[8 * PADK]);
                a2[mt] = __float_as_uint(ap[4]);
                a3[mt] = __float_as_uint(ap[8 * PADK + 4]);
            }
            #pragma unroll
            for (int nt = 0; nt < 4; nt++) {
                const float* bp = sW + (wj * 32 + nt * 8 + gi) * PADK + k0 + qi;
                unsigned b0 = __float_as_uint(bp[0]);
                unsigned b1 = __float_as_uint(bp[4]);
                #pragma unroll
                for (int mt = 0; mt < 2; mt++)
                    mma_tf32(acc[mt][nt], a0[mt], a1[mt], a2[mt], a3[mt], b0, b1);
            }
        }
        __syncthreads();

        int nx = it + NSTAGE - 1;
        if (nx < ITERS) {
            int koff = nx * BK1;
            int sn = nx % NSTAGE;
            unsigned sb = (unsigned)(sn * STG_SZ * 4);
            #pragma unroll
            for (int i = 0; i < 4; i++) cp16(wdst[i] + sb, wsrc[i] + koff);
            #pragma unroll
            for (int i = 0; i < 2; i++) cp16(xdst[i] + sb, xsrc[i] + koff);
        }
        asm volatile("cp.async.commit_group;\n");
    }

    // epilogue: split-K atomic accumulate into fp32 h[m][j]
    #pragma unroll
    for (int mt = 0; mt < 2; mt++) {
        #pragma unroll
        for (int nt = 0; nt < 4; nt++) {
            int m = wm * 32 + mt * 16 + gi;
            int j = jbase + wj * 32 + nt * 8 + qi * 2;
            if (j < Hh) {
                atomicAdd(&g_h[m * Hh + j],           acc[mt][nt][0]);
                atomicAdd(&g_h[m * Hh + j + 1],       acc[mt][nt][1]);
                atomicAdd(&g_h[(m + 8) * Hh + j],     acc[mt][nt][2]);
                atomicAdd(&g_h[(m + 8) * Hh + j + 1], acc[mt][nt][3]);
            }
        }
    }
}

// ---------------------------------------------------------------------------
// Kernel 4: GEMM2 + bias + relu fused
// ---------------------------------------------------------------------------
__global__ void k_gemm2(const float* __restrict__ b1, const float* __restrict__ W2,
                        const float* __restrict__ b2) {
    int m = blockIdx.x, tid = threadIdx.x;
    const float* hp = g_h + (size_t)m * Hh;
    float s = 0.f;
    for (int j = tid * 4; j < Hh; j += 1024) {
        float4 hv = *(const float4*)(hp + j);
        float4 bv = *(const float4*)(b1 + j);
        float4 wv = *(const float4*)(W2 + j);
        s += fmaxf(hv.x + bv.x, 0.f) * wv.x;
        s += fmaxf(hv.y + bv.y, 0.f) * wv.y;
        s += fmaxf(hv.z + bv.z, 0.f) * wv.z;
        s += fmaxf(hv.w + bv.w, 0.f) * wv.w;
    }
    #pragma unroll
    for (int o = 16; o > 0; o >>= 1) s += __shfl_down_sync(0xffffffffu, s, o);
    __shared__ float red[8];
    if ((tid & 31) == 0) red[tid >> 5] = s;
    __syncthreads();
    if (tid < 8) {
        s = red[tid];
        #pragma unroll
        for (int o = 4; o > 0; o >>= 1) s += __shfl_down_sync(0xffu, s, o);
        if (tid == 0) g_logits[m] = s + b2[0];
    }
}

// ---------------------------------------------------------------------------
// Kernel 5: BCE-with-logits loss vs target=1
// ---------------------------------------------------------------------------
__global__ void k_loss(float* __restrict__ out) {
    int tid = threadIdx.x;  // 64 threads
    float l = g_logits[tid];
    float per = (l > 0.f) ? log1pf(expf(-l)) : (log1pf(expf(l)) - l);
    #pragma unroll
    for (int o = 16; o > 0; o >>= 1) per += __shfl_down_sync(0xffffffffu, per, o);
    __shared__ float r2[2];
    if ((tid & 31) == 0) r2[tid >> 5] = per;
    __syncthreads();
    if (tid == 0) out[0] = (r2[0] + r2[1]) * (1.0f / Bb);
}

// ---------------------------------------------------------------------------
extern "C" void kernel_launch(void* const* d_in, const int* in_sizes, int n_in,
                              void* d_out, int out_size) {
    const float* feat     = (const float*)d_in[0];
    const float* w        = (const float*)d_in[3];
    const float* bn_gamma = (const float*)d_in[4];
    const float* bn_beta  = (const float*)d_in[5];
    const float* bn_mean  = (const float*)d_in[6];
    const float* bn_var   = (const float*)d_in[7];
    const float* W1       = (const float*)d_in[8];
    const float* b1       = (const float*)d_in[9];
    const float* W2       = (const float*)d_in[10];
    const float* b2       = (const float*)d_in[11];

    cudaFuncSetAttribute(k_gemm1, cudaFuncAttributeMaxDynamicSharedMemorySize, SMEM1_BYTES);

    k_zero<<<(Bb * Hh + 255) / 256, 256>>>();
    k_pool<<<Bb, 512>>>(feat, w, bn_mean, bn_var, bn_gamma, bn_beta);
    dim3 g1(63, KSPLIT);  // ceil(8000/128) x split-K
    k_gemm1<<<g1, 256, SMEM1_BYTES>>>(W1);
    k_gemm2<<<Bb, 256>>>(b1, W2, b2);
    k_loss<<<1, 64>>>((float*)d_out);
}